// round 16
// baseline (speedup 1.0000x reference)
#include <cuda_runtime.h>
#include <cstdint>

#define BSZ 8192
#define DIM 128
#define BM 64
#define BN 128
#define NBLK (BSZ / BM)     // 128
#define NTILES (BSZ / BN)   // 64
#define SA2 132             // As2 stride (words): 128 dup-words + 4 pad
#define SB 132              // Bs stride (words): 128 cols + 4 pad

typedef unsigned long long ull;

// scratch (device globals — no allocation; R1-proven minimal set)
__device__ float g_xn[BSZ * DIM];
__device__ int   g_lab[BSZ];
__device__ int   g_n1;
__device__ float g_partials[NBLK];

#define FMA2(d, a, b) asm("fma.rn.f32x2 %0, %1, %2, %0;" : "+l"(d) : "l"(a), "l"(b))

// ---------------------------------------------------------------------------
// Kernel 1: count class-1 labels (verbatim R1)
// ---------------------------------------------------------------------------
__global__ void count_kernel(const long long* __restrict__ label) {
    __shared__ int sh[256];
    int tid = threadIdx.x;
    int acc = 0;
    for (int i = tid; i < BSZ; i += 256) acc += (int)label[i];
    sh[tid] = acc;
    __syncthreads();
    for (int s = 128; s > 0; s >>= 1) {
        if (tid < s) sh[tid] += sh[tid + s];
        __syncthreads();
    }
    if (tid == 0) g_n1 = sh[0];
}

// ---------------------------------------------------------------------------
// Kernel 2: L2-normalize rows (verbatim R1)
// ---------------------------------------------------------------------------
__global__ void normalize_kernel(const float* __restrict__ data,
                                 const long long* __restrict__ label) {
    int warp = threadIdx.x >> 5;
    int lane = threadIdx.x & 31;
    int row  = blockIdx.x * 8 + warp;

    float4 v = ((const float4*)(data + (size_t)row * DIM))[lane];
    float ss = v.x * v.x + v.y * v.y + v.z * v.z + v.w * v.w;
#pragma unroll
    for (int o = 16; o; o >>= 1) ss += __shfl_xor_sync(0xffffffffu, ss, o);

    float n   = fmaxf(sqrtf(ss), 1e-12f);
    float inv = 1.0f / n;
    float4 o4 = make_float4(v.x * inv, v.y * inv, v.z * inv, v.w * inv);
    ((float4*)(g_xn + (size_t)row * DIM))[lane] = o4;

    if (lane == 0) g_lab[row] = (int)label[row];
}

// ---------------------------------------------------------------------------
// Kernel 3: fused GEMM + streaming row reductions. R14 structure; delta:
// A stored DUPLICATED in smem (pairs), FMA2 lanes = adjacent COLUMNS (native
// 64-bit pairs in B^T layout). Zero register-duplication MOVs in inner loop.
// Bitwise-identical fp32 arithmetic to R14.
// ---------------------------------------------------------------------------
__global__ __launch_bounds__(256, 1)
void main_kernel(const float* __restrict__ scale_ptr) {
    extern __shared__ float sm[];
    float* As2  = sm;                        // [DIM][SA2], A^T duplicated pairs
    float* Bs   = sm + DIM * SA2;            // [DIM][SB],  B^T
    int*   labB = (int*)(sm + DIM * SA2 + DIM * SB);

    const int tid = threadIdx.x;
    const int tx  = tid & 15;                // column group
    const int ty  = tid >> 4;                // row group (rows ty*4..ty*4+3)
    const int rowbase = blockIdx.x * BM;
    const float s = expf(*scale_ptr);

    // Load A tile once, transposed + duplicated (a -> words 2r, 2r+1)
    for (int i = tid; i < BM * DIM; i += 256) {
        int r = i >> 7, k = i & (DIM - 1);
        float v = g_xn[(size_t)(rowbase + r) * DIM + k];
        As2[k * SA2 + 2 * r]     = v;
        As2[k * SA2 + 2 * r + 1] = v;
    }

    int labR[4];
#pragma unroll
    for (int j = 0; j < 4; j++) labR[j] = g_lab[rowbase + ty * 4 + j];

    float accZ[4] = {0}, accT[4] = {0}, accS[4] = {0}, accE[4] = {0}, accQ[4] = {0};

    for (int t = 0; t < NTILES; t++) {
        __syncthreads();                     // previous chunk's Bs readers done
        const int colbase = t * BN;
        for (int i = tid; i < BN * DIM; i += 256) {
            int r = i >> 7, k = i & (DIM - 1);
            Bs[k * SB + r] = g_xn[(size_t)(colbase + r) * DIM + k];
        }
        if (tid < BN) labB[tid] = g_lab[colbase + tid];
        __syncthreads();                     // Bs + labB ready

        // acc2[j][cp]: lanes = columns (pair cp), row j
        ull acc2[4][4];
#pragma unroll
        for (int j = 0; j < 4; j++)
#pragma unroll
            for (int cp = 0; cp < 4; cp++) acc2[j][cp] = 0ull;

#pragma unroll 8
        for (int k = 0; k < DIM; k++) {
            // A dup-pairs: rows (j0,j1) in .x/.y of one 16B load (warp-broadcast)
            ulonglong2 aA = *(const ulonglong2*)&As2[k * SA2 + 8 * ty];
            ulonglong2 aB = *(const ulonglong2*)&As2[k * SA2 + 8 * ty + 4];
            // B native col-pairs: (c0,c1),(c2,c3) per 16B load
            ulonglong2 b0 = *(const ulonglong2*)&Bs[k * SB + tx * 4];
            ulonglong2 b1 = *(const ulonglong2*)&Bs[k * SB + 64 + tx * 4];
            ull a[4] = {aA.x, aA.y, aB.x, aB.y};
            ull b[4] = {b0.x, b0.y, b1.x, b1.y};
#pragma unroll
            for (int j = 0; j < 4; j++)
#pragma unroll
                for (int cp = 0; cp < 4; cp++)
                    FMA2(acc2[j][cp], a[j], b[cp]);
        }

        // unpack to the R14 epilogue view: c = cp*2+half, col order identical
        float acc[4][8];
#pragma unroll
        for (int j = 0; j < 4; j++)
#pragma unroll
            for (int cp = 0; cp < 4; cp++) {
                acc[j][2 * cp + 0] = __uint_as_float((unsigned)(acc2[j][cp] & 0xffffffffu));
                acc[j][2 * cp + 1] = __uint_as_float((unsigned)(acc2[j][cp] >> 32));
            }

        int lc[8];
#pragma unroll
        for (int c = 0; c < 8; c++) lc[c] = labB[(c >> 2) * 64 + tx * 4 + (c & 3)];

#pragma unroll
        for (int j = 0; j < 4; j++) {
#pragma unroll
            for (int c = 0; c < 8; c++) {
                float l = s * acc[j][(c >> 2) * 2 + ((c & 3) >> 1) * 4 + (c & 1) +
                                     (((c & 3) >> 1) ? 0 : 0)];
                // NOTE: col mapping — acc index for col (c>>2)*64 + tx*4 + (c&3):
                // pair cp = (c>>2)*2 + ((c&3)>>1), half = c&1
                l = s * acc[j][((c >> 2) * 2 + ((c & 3) >> 1)) * 2 + (c & 1)];
                float e = __expf(l - s);
                accZ[j] += e;
                accT[j] = fmaf(e, l, accT[j]);
                accS[j] += l;
                if (lc[c] == labR[j]) { accE[j] += e; accQ[j] += l; }
            }
        }
    }

    // Reduce across the 16-thread column group (R1 pattern)
#pragma unroll
    for (int j = 0; j < 4; j++) {
#pragma unroll
        for (int o = 8; o; o >>= 1) {
            accZ[j] += __shfl_xor_sync(0xffffffffu, accZ[j], o);
            accT[j] += __shfl_xor_sync(0xffffffffu, accT[j], o);
            accS[j] += __shfl_xor_sync(0xffffffffu, accS[j], o);
            accE[j] += __shfl_xor_sync(0xffffffffu, accE[j], o);
            accQ[j] += __shfl_xor_sync(0xffffffffu, accQ[j], o);
        }
    }

    __shared__ float red[16];
    if (tx == 0) {
        const int n1 = g_n1;
        double total = 0.0;
#pragma unroll
        for (int j = 0; j < 4; j++) {
            int ci = labR[j] ? n1 : (BSZ - n1);
            double cd  = (double)ci;
            double ic  = 1.0 / cd;
            double eic = exp(ic);
            double Dd  = cd * eic + (double)(BSZ - ci);
            double qd  = 1.0 / Dd;
            double qs  = eic / Dd;
            double Z   = (double)accZ[j];
            double v   = qs + (double)accT[j] / Z
                       - qd * (double)accS[j]
                       - (qs - qd) * (double)accQ[j]
                       - ((double)accE[j] / Z) * ic;
            total += v;
        }
        red[ty] = (float)total;
    }
    __syncthreads();
    if (tid == 0) {
        float sum = 0.f;
#pragma unroll
        for (int i = 0; i < 16; i++) sum += red[i];
        g_partials[blockIdx.x] = sum;
    }
}

// ---------------------------------------------------------------------------
// Kernel 4: deterministic final reduction (verbatim R1)
// ---------------------------------------------------------------------------
__global__ void final_kernel(float* __restrict__ out) {
    __shared__ float sh[128];
    int tid = threadIdx.x;
    sh[tid] = g_partials[tid];
    __syncthreads();
    for (int s = 64; s > 0; s >>= 1) {
        if (tid < s) sh[tid] += sh[tid + s];
        __syncthreads();
    }
    if (tid == 0) out[0] = sh[0] / (2.0f * (float)BSZ);
}

// ---------------------------------------------------------------------------
extern "C" void kernel_launch(void* const* d_in, const int* in_sizes, int n_in,
                              void* d_out, int out_size) {
    const float*     data  = (const float*)d_in[0];
    const float*     scale = (const float*)d_in[1];
    const long long* label = (const long long*)d_in[2];
    float*           out   = (float*)d_out;

    size_t smem = (size_t)(DIM * SA2 + DIM * SB) * sizeof(float) + BN * sizeof(int);
    cudaFuncSetAttribute(main_kernel, cudaFuncAttributeMaxDynamicSharedMemorySize,
                         (int)smem);

    count_kernel<<<1, 256>>>(label);
    normalize_kernel<<<BSZ / 8, 256>>>(data, label);
    main_kernel<<<NBLK, 256, smem>>>(scale);
    final_kernel<<<1, 128>>>(out);
}